// round 8
// baseline (speedup 1.0000x reference)
#include <cuda_runtime.h>
#include <cstdint>

// Problem constants (fixed shapes per reference setup_inputs)
#define B_    2
#define H_    32
#define S_    4096
#define D_    128
#define U_    16
#define TQ    3968        // S - RESID - (S % GROUP)
#define NG    31          // TQ / GROUP
#define RROWS 257         // 2*RESID + 1

// Output region offsets (float32 elements, concatenated in reference return order)
static constexpr size_t LEN_QK  = (size_t)B_ * H_ * (TQ / 4) * D_;   // 8,126,464
static constexpr size_t LEN_SC  = (size_t)B_ * H_ * NG * D_;         // 253,952
static constexpr size_t LEN_QV  = (size_t)B_ * H_ * (D_ / 4) * TQ;   // 8,126,464
static constexpr size_t LEN_VSC = (size_t)B_ * H_ * TQ;              // 253,952
static constexpr size_t LEN_R   = (size_t)B_ * H_ * RROWS * D_;      // 2,105,344
static constexpr size_t LEN_F   = (size_t)B_ * H_ * S_ * D_;         // 33,554,432 = 2^25

static constexpr size_t OFF_QK = 0;
static constexpr size_t OFF_KS = OFF_QK + LEN_QK;
static constexpr size_t OFF_KM = OFF_KS + LEN_SC;
static constexpr size_t OFF_QV = OFF_KM + LEN_SC;
static constexpr size_t OFF_VS = OFF_QV + LEN_QV;
static constexpr size_t OFF_VM = OFF_VS + LEN_VSC;
static constexpr size_t OFF_KR = OFF_VM + LEN_VSC;
static constexpr size_t OFF_VR = OFF_KR + LEN_R;
static constexpr size_t OFF_KF = OFF_VR + LEN_R;
static constexpr size_t OFF_VF = OFF_KF + LEN_F;

// Work list: K-quant, V-quant, residual items, full-cache chunks (256-thr CTA)
static constexpr int NK  = B_ * H_ * NG;        // 1984
static constexpr int NV  = B_ * H_ * NG;        // 1984
static constexpr int NR  = 2 * B_ * H_;         // 128 residual items (k/v × bh)
static constexpr int FULL_CHUNK4 = 2048;        // float4 per full-cache chunk (32 KB)
static constexpr int NF  = (int)(2 * LEN_F / (4 * FULL_CHUNK4));  // 8192
static constexpr int NITEMS = NK + NV + NR + NF;                  // 12288

static constexpr int GRID_ = 888;   // 6 CTAs/SM on 148 SMs

__global__ __launch_bounds__(256, 6)
void mega_kernel(const float* __restrict__ k, const float* __restrict__ v,
                 const float* __restrict__ kn, const float* __restrict__ vn,
                 const int* __restrict__ cs, const int* __restrict__ qcs,
                 float* __restrict__ out)
{
    __shared__ float4 smn[8][32];             // K: per-q-slice column minima
    __shared__ float4 smx[8][32];
    __shared__ unsigned short smq[128][34];   // V: pitch 34 transpose buffer
    __shared__ float ssc[128];
    __shared__ float smin[128];

    const int tid = threadIdx.x;

    for (int item = blockIdx.x; item < NITEMS; item += GRID_) {
        if (item < NK) {
            // ------------- K quant (two-pass): group of 128 seq rows -----------
            // Thread = (d4 in 0..31, q in 0..7); q-slice = 16 seq rows.
            __syncthreads();   // protect smn/smx reuse across items
            const int bh = item / NG;
            const int g  = item - bh * NG;
            const int d4 = tid & 31;          // float4 column, d = 4*d4
            const int q  = tid >> 5;          // 0..7

            const float4* __restrict__ base = (const float4*)(
                k + (((size_t)bh) * S_ + (size_t)g * 128) * D_) + d4;

            // Pass 1: min/max only (no value array -> low registers)
            float4 mn4 = make_float4(3.4e38f, 3.4e38f, 3.4e38f, 3.4e38f);
            float4 mx4 = make_float4(-3.4e38f, -3.4e38f, -3.4e38f, -3.4e38f);
#pragma unroll
            for (int it = 0; it < 16; it++) {
                float4 x = base[(size_t)(q * 16 + it) * (D_ / 4)];
                mn4.x = fminf(mn4.x, x.x); mn4.y = fminf(mn4.y, x.y);
                mn4.z = fminf(mn4.z, x.z); mn4.w = fminf(mn4.w, x.w);
                mx4.x = fmaxf(mx4.x, x.x); mx4.y = fmaxf(mx4.y, x.y);
                mx4.z = fmaxf(mx4.z, x.z); mx4.w = fmaxf(mx4.w, x.w);
            }
            smn[q][d4] = mn4;
            smx[q][d4] = mx4;
            __syncthreads();
#pragma unroll
            for (int p = 0; p < 8; p++) {
                float4 a = smn[p][d4], bb = smx[p][d4];
                mn4.x = fminf(mn4.x, a.x); mn4.y = fminf(mn4.y, a.y);
                mn4.z = fminf(mn4.z, a.z); mn4.w = fminf(mn4.w, a.w);
                mx4.x = fmaxf(mx4.x, bb.x); mx4.y = fmaxf(mx4.y, bb.y);
                mx4.z = fmaxf(mx4.z, bb.z); mx4.w = fmaxf(mx4.w, bb.w);
            }
            float4 sc4, iv4;
            sc4.x = fmaxf(__fdiv_rn(mx4.x - mn4.x, 15.0f), 1e-6f);
            sc4.y = fmaxf(__fdiv_rn(mx4.y - mn4.y, 15.0f), 1e-6f);
            sc4.z = fmaxf(__fdiv_rn(mx4.z - mn4.z, 15.0f), 1e-6f);
            sc4.w = fmaxf(__fdiv_rn(mx4.w - mn4.w, 15.0f), 1e-6f);
            iv4.x = __fdiv_rn(1.0f, sc4.x);
            iv4.y = __fdiv_rn(1.0f, sc4.y);
            iv4.z = __fdiv_rn(1.0f, sc4.z);
            iv4.w = __fdiv_rn(1.0f, sc4.w);

            if (q == 0) {
                size_t si = (((size_t)bh) * NG + g) * D_ + 4 * d4;
                *(float4*)(out + OFF_KS + si) = sc4;
                *(float4*)(out + OFF_KM + si) = mn4;
            }

            // Pass 2: re-read (L2-resident) + pack. 4 packed rows per thread.
            float* __restrict__ po = out + OFF_QK;
            const size_t rowbase = ((size_t)bh) * (TQ / 4) + (size_t)g * 32 + (size_t)q * 4;
#pragma unroll
            for (int j = 0; j < 4; j++) {
                float4 r0 = base[(size_t)(q * 16 + 4 * j + 0) * (D_ / 4)];
                float4 r1 = base[(size_t)(q * 16 + 4 * j + 1) * (D_ / 4)];
                float4 r2 = base[(size_t)(q * 16 + 4 * j + 2) * (D_ / 4)];
                float4 r3 = base[(size_t)(q * 16 + 4 * j + 3) * (D_ / 4)];
                float4 w;
                {
                    int c0 = (int)rintf((r0.x - mn4.x) * iv4.x);
                    int c1 = (int)rintf((r1.x - mn4.x) * iv4.x);
                    int c2 = (int)rintf((r2.x - mn4.x) * iv4.x);
                    int c3 = (int)rintf((r3.x - mn4.x) * iv4.x);
                    c0 = c0 < 0 ? 0 : (c0 > 15 ? 15 : c0);
                    c1 = c1 < 0 ? 0 : (c1 > 15 ? 15 : c1);
                    c2 = c2 < 0 ? 0 : (c2 > 15 ? 15 : c2);
                    c3 = c3 < 0 ? 0 : (c3 > 15 ? 15 : c3);
                    w.x = (float)((unsigned)c0 | ((unsigned)c1 << 4) |
                                  ((unsigned)c2 << 8) | ((unsigned)c3 << 12));
                }
                {
                    int c0 = (int)rintf((r0.y - mn4.y) * iv4.y);
                    int c1 = (int)rintf((r1.y - mn4.y) * iv4.y);
                    int c2 = (int)rintf((r2.y - mn4.y) * iv4.y);
                    int c3 = (int)rintf((r3.y - mn4.y) * iv4.y);
                    c0 = c0 < 0 ? 0 : (c0 > 15 ? 15 : c0);
                    c1 = c1 < 0 ? 0 : (c1 > 15 ? 15 : c1);
                    c2 = c2 < 0 ? 0 : (c2 > 15 ? 15 : c2);
                    c3 = c3 < 0 ? 0 : (c3 > 15 ? 15 : c3);
                    w.y = (float)((unsigned)c0 | ((unsigned)c1 << 4) |
                                  ((unsigned)c2 << 8) | ((unsigned)c3 << 12));
                }
                {
                    int c0 = (int)rintf((r0.z - mn4.z) * iv4.z);
                    int c1 = (int)rintf((r1.z - mn4.z) * iv4.z);
                    int c2 = (int)rintf((r2.z - mn4.z) * iv4.z);
                    int c3 = (int)rintf((r3.z - mn4.z) * iv4.z);
                    c0 = c0 < 0 ? 0 : (c0 > 15 ? 15 : c0);
                    c1 = c1 < 0 ? 0 : (c1 > 15 ? 15 : c1);
                    c2 = c2 < 0 ? 0 : (c2 > 15 ? 15 : c2);
                    c3 = c3 < 0 ? 0 : (c3 > 15 ? 15 : c3);
                    w.z = (float)((unsigned)c0 | ((unsigned)c1 << 4) |
                                  ((unsigned)c2 << 8) | ((unsigned)c3 << 12));
                }
                {
                    int c0 = (int)rintf((r0.w - mn4.w) * iv4.w);
                    int c1 = (int)rintf((r1.w - mn4.w) * iv4.w);
                    int c2 = (int)rintf((r2.w - mn4.w) * iv4.w);
                    int c3 = (int)rintf((r3.w - mn4.w) * iv4.w);
                    c0 = c0 < 0 ? 0 : (c0 > 15 ? 15 : c0);
                    c1 = c1 < 0 ? 0 : (c1 > 15 ? 15 : c1);
                    c2 = c2 < 0 ? 0 : (c2 > 15 ? 15 : c2);
                    c3 = c3 < 0 ? 0 : (c3 > 15 ? 15 : c3);
                    w.w = (float)((unsigned)c0 | ((unsigned)c1 << 4) |
                                  ((unsigned)c2 << 8) | ((unsigned)c3 << 12));
                }
                *(float4*)(po + (rowbase + j) * D_ + 4 * d4) = w;
            }
        } else if (item < NK + NV) {
            // ---------------- V quant: group = full head_dim, per token --------
            // 8 warps x 16 tokens, processed in 4 batches of 4 (MLP=4).
            __syncthreads();   // protect smq/ssc/smin reuse across items
            const int vi = item - NK;
            const int bh = vi / NG;
            const int g  = vi - bh * NG;
            const int lane = tid & 31;
            const int warp = tid >> 5;       // 8 warps, 16 tokens each

            const float* __restrict__ base =
                v + (((size_t)bh) * S_ + (size_t)g * 128) * D_ + lane * 4;

#pragma unroll
            for (int p = 0; p < 4; p++) {
                const int tlb = warp * 16 + 4 * p;
                float4 va0 = *(const float4*)(base + (size_t)(tlb + 0) * D_);
                float4 va1 = *(const float4*)(base + (size_t)(tlb + 1) * D_);
                float4 va2 = *(const float4*)(base + (size_t)(tlb + 2) * D_);
                float4 va3 = *(const float4*)(base + (size_t)(tlb + 3) * D_);

                float mn0 = fminf(fminf(va0.x, va0.y), fminf(va0.z, va0.w));
                float mx0 = fmaxf(fmaxf(va0.x, va0.y), fmaxf(va0.z, va0.w));
                float mn1 = fminf(fminf(va1.x, va1.y), fminf(va1.z, va1.w));
                float mx1 = fmaxf(fmaxf(va1.x, va1.y), fmaxf(va1.z, va1.w));
                float mn2 = fminf(fminf(va2.x, va2.y), fminf(va2.z, va2.w));
                float mx2 = fmaxf(fmaxf(va2.x, va2.y), fmaxf(va2.z, va2.w));
                float mn3 = fminf(fminf(va3.x, va3.y), fminf(va3.z, va3.w));
                float mx3 = fmaxf(fmaxf(va3.x, va3.y), fmaxf(va3.z, va3.w));
#pragma unroll
                for (int o = 16; o > 0; o >>= 1) {
                    mn0 = fminf(mn0, __shfl_xor_sync(0xFFFFFFFFu, mn0, o));
                    mn1 = fminf(mn1, __shfl_xor_sync(0xFFFFFFFFu, mn1, o));
                    mn2 = fminf(mn2, __shfl_xor_sync(0xFFFFFFFFu, mn2, o));
                    mn3 = fminf(mn3, __shfl_xor_sync(0xFFFFFFFFu, mn3, o));
                    mx0 = fmaxf(mx0, __shfl_xor_sync(0xFFFFFFFFu, mx0, o));
                    mx1 = fmaxf(mx1, __shfl_xor_sync(0xFFFFFFFFu, mx1, o));
                    mx2 = fmaxf(mx2, __shfl_xor_sync(0xFFFFFFFFu, mx2, o));
                    mx3 = fmaxf(mx3, __shfl_xor_sync(0xFFFFFFFFu, mx3, o));
                }
#pragma unroll
                for (int t = 0; t < 4; t++) {
                    float mn = t == 0 ? mn0 : (t == 1 ? mn1 : (t == 2 ? mn2 : mn3));
                    float mx = t == 0 ? mx0 : (t == 1 ? mx1 : (t == 2 ? mx2 : mx3));
                    float4 x = t == 0 ? va0 : (t == 1 ? va1 : (t == 2 ? va2 : va3));
                    const float scale = fmaxf(__fdiv_rn(mx - mn, 15.0f), 1e-6f);
                    const float inv   = __fdiv_rn(1.0f, scale);
                    int c0 = (int)rintf((x.x - mn) * inv);
                    int c1 = (int)rintf((x.y - mn) * inv);
                    int c2 = (int)rintf((x.z - mn) * inv);
                    int c3 = (int)rintf((x.w - mn) * inv);
                    c0 = c0 < 0 ? 0 : (c0 > 15 ? 15 : c0);
                    c1 = c1 < 0 ? 0 : (c1 > 15 ? 15 : c1);
                    c2 = c2 < 0 ? 0 : (c2 > 15 ? 15 : c2);
                    c3 = c3 < 0 ? 0 : (c3 > 15 ? 15 : c3);
                    smq[tlb + t][lane] =
                        (unsigned short)((unsigned)c0 | ((unsigned)c1 << 4) |
                                         ((unsigned)c2 << 8) | ((unsigned)c3 << 12));
                    if (lane == 0) { ssc[tlb + t] = scale; smin[tlb + t] = mn; }
                }
            }
            __syncthreads();

            const size_t tbase = ((size_t)bh) * TQ + (size_t)g * 128;
            if (tid < 128) {
                out[OFF_VS + tbase + tid] = ssc[tid];
                out[OFF_VM + tbase + tid] = smin[tid];
            }
            // Vectorized transpose writeback: one float4 = 4 consecutive tokens.
            const size_t qvbase = ((size_t)bh) * 32 * TQ + (size_t)g * 128;
#pragma unroll
            for (int i = tid; i < 1024; i += 256) {
                const int d4 = i >> 5;        // 0..31
                const int tl = (i & 31) * 4;  // token base
                float4 w;
                w.x = (float)smq[tl + 0][d4];
                w.y = (float)smq[tl + 1][d4];
                w.z = (float)smq[tl + 2][d4];
                w.w = (float)smq[tl + 3][d4];
                *(float4*)(out + OFF_QV + qvbase + (size_t)d4 * TQ + tl) = w;
            }
        } else if (item < NK + NV + NR) {
            // ---------------- Residual item: one (k/v, bh) buffer ---------------
            const int ri   = item - NK - NV;
            const int half = ri >> 6;            // 0 = k, 1 = v
            const int bh   = ri & 63;

            const float* __restrict__ src =
                (half ? v : k) + (((size_t)bh) * S_ + TQ) * D_;
            float* __restrict__ dstf =
                out + (half ? OFF_VR : OFF_KR) + ((size_t)bh) * RROWS * D_;

            // rows 0..127: streaming copy, 4096 float4
            const float4* __restrict__ s4 = (const float4*)src;
            float4* __restrict__ d4p = (float4*)dstf;
#pragma unroll
            for (int j = 0; j < 16; j++)
                d4p[tid + j * 256] = s4[tid + j * 256];

            // rows 128..256: zero, 4128 float4
            float4* __restrict__ z4 = (float4*)(dstf + 128 * D_);
            const float4 z = make_float4(0.f, 0.f, 0.f, 0.f);
#pragma unroll
            for (int j = 0; j < 16; j++)
                z4[tid + j * 256] = z;
            if (tid < 32) z4[tid + 16 * 256] = z;
        } else {
            // ---------------- Full-cache chunk: zero (+ scatter overlap) --------
            const int fi      = item - NK - NV - NR;       // 0..8191
            const int half    = fi >> 12;                  // 4096 chunks per half
            const int c       = fi & 4095;
            const int bh      = c >> 6;
            const int sb      = c & 63;                    // 64 seq rows per chunk

            float* __restrict__ dstf =
                out + (half ? OFF_VF : OFF_KF) +
                ((size_t)bh) * (S_ * D_) + (size_t)sb * (64 * D_);
            float4* __restrict__ d4p = (float4*)dstf;

            const float4 z = make_float4(0.f, 0.f, 0.f, 0.f);
#pragma unroll
            for (int j = 0; j < 8; j++)
                d4p[tid + j * 256] = z;

            if (sb < 2) {
                // Scatter rows [off, off+16) may intersect this chunk's rows
                // [64*sb, 64*sb+64) (off in 0..63, so chunks 0 and 1 only).
                __syncthreads();   // order scatter after this CTA's zeroes
                const int b   = bh >> 5;
                const int off = cs[b] - qcs[b];
                const float* __restrict__ src =
                    (half ? vn : kn) + ((size_t)bh) * (U_ * D_);
#pragma unroll
                for (int i = tid; i < 512; i += 256) {
                    const int u  = i >> 5;            // 0..15
                    const int dd = i & 31;
                    const int r  = off + u;
                    if ((r >> 6) == sb) {
                        *(float4*)(out + (half ? OFF_VF : OFF_KF) +
                                   ((size_t)bh) * (S_ * D_) + (size_t)r * D_ + dd * 4) =
                            *(const float4*)(src + (size_t)u * D_ + dd * 4);
                    }
                }
            }
        }
    }
}

// ---------------------------------------------------------------------------
extern "C" void kernel_launch(void* const* d_in, const int* in_sizes, int n_in,
                              void* d_out, int out_size) {
    const float* k     = (const float*)d_in[0];
    const float* v     = (const float*)d_in[1];
    const float* k_new = (const float*)d_in[2];
    const float* v_new = (const float*)d_in[3];
    const int*   cs    = (const int*)d_in[4];
    const int*   qcs   = (const int*)d_in[5];
    float* out = (float*)d_out;

    (void)in_sizes; (void)n_in; (void)out_size;

    mega_kernel<<<GRID_, 256>>>(k, v, k_new, v_new, cs, qcs, out);
}

// round 9
// speedup vs baseline: 1.3302x; 1.3302x over previous
#include <cuda_runtime.h>
#include <cstdint>

// Problem constants (fixed shapes per reference setup_inputs)
#define B_    2
#define H_    32
#define S_    4096
#define D_    128
#define U_    16
#define TQ    3968        // S - RESID - (S % GROUP)
#define NG    31          // TQ / GROUP
#define RROWS 257         // 2*RESID + 1

// Output region offsets (float32 elements, concatenated in reference return order)
static constexpr size_t LEN_QK  = (size_t)B_ * H_ * (TQ / 4) * D_;   // 8,126,464
static constexpr size_t LEN_SC  = (size_t)B_ * H_ * NG * D_;         // 253,952
static constexpr size_t LEN_QV  = (size_t)B_ * H_ * (D_ / 4) * TQ;   // 8,126,464
static constexpr size_t LEN_VSC = (size_t)B_ * H_ * TQ;              // 253,952
static constexpr size_t LEN_R   = (size_t)B_ * H_ * RROWS * D_;      // 2,105,344
static constexpr size_t LEN_F   = (size_t)B_ * H_ * S_ * D_;         // 33,554,432 = 2^25

static constexpr size_t OFF_QK = 0;
static constexpr size_t OFF_KS = OFF_QK + LEN_QK;
static constexpr size_t OFF_KM = OFF_KS + LEN_SC;
static constexpr size_t OFF_QV = OFF_KM + LEN_SC;
static constexpr size_t OFF_VS = OFF_QV + LEN_QV;
static constexpr size_t OFF_VM = OFF_VS + LEN_VSC;
static constexpr size_t OFF_KR = OFF_VM + LEN_VSC;
static constexpr size_t OFF_VR = OFF_KR + LEN_R;
static constexpr size_t OFF_KF = OFF_VR + LEN_R;
static constexpr size_t OFF_VF = OFF_KF + LEN_F;

// Work list: K-quant, V-quant, residual items, full-cache chunks (512-thr CTA)
static constexpr int NK  = B_ * H_ * NG;        // 1984
static constexpr int NV  = B_ * H_ * NG;        // 1984
static constexpr int NR  = 2 * B_ * H_;         // 128 residual items (k/v × bh)
static constexpr int FULL_CHUNK4 = 4096;        // float4 per full-cache chunk (64 KB)
static constexpr int NF  = (int)(2 * LEN_F / (4 * FULL_CHUNK4));  // 4096
static constexpr int NITEMS = NK + NV + NR + NF;                  // 8192

static constexpr int GRID_ = 296;   // 2 CTAs/SM on 148 SMs

__global__ __launch_bounds__(512, 2)
void mega_kernel(const float* __restrict__ k, const float* __restrict__ v,
                 const float* __restrict__ kn, const float* __restrict__ vn,
                 const int* __restrict__ cs, const int* __restrict__ qcs,
                 float* __restrict__ out)
{
    __shared__ float4 smn[16][32];            // K: per-q-slice column minima
    __shared__ float4 smx[16][32];
    __shared__ unsigned short smq[128][34];   // V: pitch 34 transpose buffer
    __shared__ float ssc[128];
    __shared__ float smin[128];

    const int tid = threadIdx.x;

    for (int item = blockIdx.x; item < NITEMS; item += GRID_) {
        if (item < NK) {
            // ------------- K quant (single-pass, float4): 128 seq rows ---------
            // Thread = (d4 in 0..31, q in 0..15); q-slice = 8 seq rows in regs.
            __syncthreads();   // protect smn/smx reuse across items
            const int bh = item / NG;
            const int g  = item - bh * NG;
            const int d4 = tid & 31;          // float4 column, d = 4*d4
            const int q  = tid >> 5;          // 0..15

            const float4* __restrict__ base = (const float4*)(
                k + (((size_t)bh) * S_ + (size_t)g * 128) * D_) + d4;

            float4 vals[8];
            float4 mn4 = make_float4(3.4e38f, 3.4e38f, 3.4e38f, 3.4e38f);
            float4 mx4 = make_float4(-3.4e38f, -3.4e38f, -3.4e38f, -3.4e38f);
#pragma unroll
            for (int it = 0; it < 8; it++) {
                float4 x = base[(size_t)(q * 8 + it) * (D_ / 4)];
                vals[it] = x;
                mn4.x = fminf(mn4.x, x.x); mn4.y = fminf(mn4.y, x.y);
                mn4.z = fminf(mn4.z, x.z); mn4.w = fminf(mn4.w, x.w);
                mx4.x = fmaxf(mx4.x, x.x); mx4.y = fmaxf(mx4.y, x.y);
                mx4.z = fmaxf(mx4.z, x.z); mx4.w = fmaxf(mx4.w, x.w);
            }
            smn[q][d4] = mn4;
            smx[q][d4] = mx4;
            __syncthreads();
#pragma unroll
            for (int p = 0; p < 16; p++) {
                float4 a = smn[p][d4], bb = smx[p][d4];
                mn4.x = fminf(mn4.x, a.x); mn4.y = fminf(mn4.y, a.y);
                mn4.z = fminf(mn4.z, a.z); mn4.w = fminf(mn4.w, a.w);
                mx4.x = fmaxf(mx4.x, bb.x); mx4.y = fmaxf(mx4.y, bb.y);
                mx4.z = fmaxf(mx4.z, bb.z); mx4.w = fmaxf(mx4.w, bb.w);
            }
            float4 sc4, iv4;
            sc4.x = fmaxf(__fdiv_rn(mx4.x - mn4.x, 15.0f), 1e-6f);
            sc4.y = fmaxf(__fdiv_rn(mx4.y - mn4.y, 15.0f), 1e-6f);
            sc4.z = fmaxf(__fdiv_rn(mx4.z - mn4.z, 15.0f), 1e-6f);
            sc4.w = fmaxf(__fdiv_rn(mx4.w - mn4.w, 15.0f), 1e-6f);
            iv4.x = __fdiv_rn(1.0f, sc4.x);
            iv4.y = __fdiv_rn(1.0f, sc4.y);
            iv4.z = __fdiv_rn(1.0f, sc4.z);
            iv4.w = __fdiv_rn(1.0f, sc4.w);

            if (q == 0) {
                size_t si = (((size_t)bh) * NG + g) * D_ + 4 * d4;
                *(float4*)(out + OFF_KS + si) = sc4;
                *(float4*)(out + OFF_KM + si) = mn4;
            }

            // Pack from registers: 2 packed rows per thread (float4 each).
            float* __restrict__ po = out + OFF_QK;
            const size_t rowbase = ((size_t)bh) * (TQ / 4) + (size_t)g * 32 + (size_t)q * 2;
#pragma unroll
            for (int j = 0; j < 2; j++) {
                float4 r0 = vals[4 * j + 0];
                float4 r1 = vals[4 * j + 1];
                float4 r2 = vals[4 * j + 2];
                float4 r3 = vals[4 * j + 3];
                float4 w;
                {
                    int c0 = (int)rintf((r0.x - mn4.x) * iv4.x);
                    int c1 = (int)rintf((r1.x - mn4.x) * iv4.x);
                    int c2 = (int)rintf((r2.x - mn4.x) * iv4.x);
                    int c3 = (int)rintf((r3.x - mn4.x) * iv4.x);
                    c0 = c0 < 0 ? 0 : (c0 > 15 ? 15 : c0);
                    c1 = c1 < 0 ? 0 : (c1 > 15 ? 15 : c1);
                    c2 = c2 < 0 ? 0 : (c2 > 15 ? 15 : c2);
                    c3 = c3 < 0 ? 0 : (c3 > 15 ? 15 : c3);
                    w.x = (float)((unsigned)c0 | ((unsigned)c1 << 4) |
                                  ((unsigned)c2 << 8) | ((unsigned)c3 << 12));
                }
                {
                    int c0 = (int)rintf((r0.y - mn4.y) * iv4.y);
                    int c1 = (int)rintf((r1.y - mn4.y) * iv4.y);
                    int c2 = (int)rintf((r2.y - mn4.y) * iv4.y);
                    int c3 = (int)rintf((r3.y - mn4.y) * iv4.y);
                    c0 = c0 < 0 ? 0 : (c0 > 15 ? 15 : c0);
                    c1 = c1 < 0 ? 0 : (c1 > 15 ? 15 : c1);
                    c2 = c2 < 0 ? 0 : (c2 > 15 ? 15 : c2);
                    c3 = c3 < 0 ? 0 : (c3 > 15 ? 15 : c3);
                    w.y = (float)((unsigned)c0 | ((unsigned)c1 << 4) |
                                  ((unsigned)c2 << 8) | ((unsigned)c3 << 12));
                }
                {
                    int c0 = (int)rintf((r0.z - mn4.z) * iv4.z);
                    int c1 = (int)rintf((r1.z - mn4.z) * iv4.z);
                    int c2 = (int)rintf((r2.z - mn4.z) * iv4.z);
                    int c3 = (int)rintf((r3.z - mn4.z) * iv4.z);
                    c0 = c0 < 0 ? 0 : (c0 > 15 ? 15 : c0);
                    c1 = c1 < 0 ? 0 : (c1 > 15 ? 15 : c1);
                    c2 = c2 < 0 ? 0 : (c2 > 15 ? 15 : c2);
                    c3 = c3 < 0 ? 0 : (c3 > 15 ? 15 : c3);
                    w.z = (float)((unsigned)c0 | ((unsigned)c1 << 4) |
                                  ((unsigned)c2 << 8) | ((unsigned)c3 << 12));
                }
                {
                    int c0 = (int)rintf((r0.w - mn4.w) * iv4.w);
                    int c1 = (int)rintf((r1.w - mn4.w) * iv4.w);
                    int c2 = (int)rintf((r2.w - mn4.w) * iv4.w);
                    int c3 = (int)rintf((r3.w - mn4.w) * iv4.w);
                    c0 = c0 < 0 ? 0 : (c0 > 15 ? 15 : c0);
                    c1 = c1 < 0 ? 0 : (c1 > 15 ? 15 : c1);
                    c2 = c2 < 0 ? 0 : (c2 > 15 ? 15 : c2);
                    c3 = c3 < 0 ? 0 : (c3 > 15 ? 15 : c3);
                    w.w = (float)((unsigned)c0 | ((unsigned)c1 << 4) |
                                  ((unsigned)c2 << 8) | ((unsigned)c3 << 12));
                }
                *(float4*)(po + (rowbase + j) * D_ + 4 * d4) = w;
            }
        } else if (item < NK + NV) {
            // ---------------- V quant: group = full head_dim, per token --------
            // 16 warps x 8 tokens, all 8 loaded up-front (MLP=8), paired chains.
            __syncthreads();   // protect smq/ssc/smin reuse across items
            const int vi = item - NK;
            const int bh = vi / NG;
            const int g  = vi - bh * NG;
            const int lane = tid & 31;
            const int warp = tid >> 5;       // 16 warps, 8 tokens each

            const float* __restrict__ base =
                v + (((size_t)bh) * S_ + (size_t)g * 128) * D_ + lane * 4;

            float4 va[8];
#pragma unroll
            for (int it = 0; it < 8; it++)
                va[it] = *(const float4*)(base + (size_t)(warp * 8 + it) * D_);

#pragma unroll
            for (int p = 0; p < 4; p++) {
                const int tl0 = warp * 8 + 2 * p;
                const int tl1 = tl0 + 1;
                float4 x0 = va[2 * p];
                float4 x1 = va[2 * p + 1];

                float mn0 = fminf(fminf(x0.x, x0.y), fminf(x0.z, x0.w));
                float mx0 = fmaxf(fmaxf(x0.x, x0.y), fmaxf(x0.z, x0.w));
                float mn1 = fminf(fminf(x1.x, x1.y), fminf(x1.z, x1.w));
                float mx1 = fmaxf(fmaxf(x1.x, x1.y), fmaxf(x1.z, x1.w));
#pragma unroll
                for (int o = 16; o > 0; o >>= 1) {
                    mn0 = fminf(mn0, __shfl_xor_sync(0xFFFFFFFFu, mn0, o));
                    mn1 = fminf(mn1, __shfl_xor_sync(0xFFFFFFFFu, mn1, o));
                    mx0 = fmaxf(mx0, __shfl_xor_sync(0xFFFFFFFFu, mx0, o));
                    mx1 = fmaxf(mx1, __shfl_xor_sync(0xFFFFFFFFu, mx1, o));
                }
                const float sc0 = fmaxf(__fdiv_rn(mx0 - mn0, 15.0f), 1e-6f);
                const float sc1 = fmaxf(__fdiv_rn(mx1 - mn1, 15.0f), 1e-6f);
                const float iv0 = __fdiv_rn(1.0f, sc0);
                const float iv1 = __fdiv_rn(1.0f, sc1);

                int a0 = (int)rintf((x0.x - mn0) * iv0);
                int a1 = (int)rintf((x0.y - mn0) * iv0);
                int a2 = (int)rintf((x0.z - mn0) * iv0);
                int a3 = (int)rintf((x0.w - mn0) * iv0);
                int b0 = (int)rintf((x1.x - mn1) * iv1);
                int b1 = (int)rintf((x1.y - mn1) * iv1);
                int b2 = (int)rintf((x1.z - mn1) * iv1);
                int b3 = (int)rintf((x1.w - mn1) * iv1);
                a0 = a0 < 0 ? 0 : (a0 > 15 ? 15 : a0);
                a1 = a1 < 0 ? 0 : (a1 > 15 ? 15 : a1);
                a2 = a2 < 0 ? 0 : (a2 > 15 ? 15 : a2);
                a3 = a3 < 0 ? 0 : (a3 > 15 ? 15 : a3);
                b0 = b0 < 0 ? 0 : (b0 > 15 ? 15 : b0);
                b1 = b1 < 0 ? 0 : (b1 > 15 ? 15 : b1);
                b2 = b2 < 0 ? 0 : (b2 > 15 ? 15 : b2);
                b3 = b3 < 0 ? 0 : (b3 > 15 ? 15 : b3);

                smq[tl0][lane] = (unsigned short)((unsigned)a0 | ((unsigned)a1 << 4) |
                                                 ((unsigned)a2 << 8) | ((unsigned)a3 << 12));
                smq[tl1][lane] = (unsigned short)((unsigned)b0 | ((unsigned)b1 << 4) |
                                                 ((unsigned)b2 << 8) | ((unsigned)b3 << 12));
                if (lane == 0) {
                    ssc[tl0] = sc0; smin[tl0] = mn0;
                    ssc[tl1] = sc1; smin[tl1] = mn1;
                }
            }
            __syncthreads();

            const size_t tbase = ((size_t)bh) * TQ + (size_t)g * 128;
            if (tid < 128) {
                out[OFF_VS + tbase + tid] = ssc[tid];
                out[OFF_VM + tbase + tid] = smin[tid];
            }
            // Vectorized transpose writeback: one float4 = 4 consecutive tokens.
            const size_t qvbase = ((size_t)bh) * 32 * TQ + (size_t)g * 128;
#pragma unroll
            for (int i = tid; i < 1024; i += 512) {
                const int d4 = i >> 5;        // 0..31
                const int tl = (i & 31) * 4;  // token base
                float4 w;
                w.x = (float)smq[tl + 0][d4];
                w.y = (float)smq[tl + 1][d4];
                w.z = (float)smq[tl + 2][d4];
                w.w = (float)smq[tl + 3][d4];
                *(float4*)(out + OFF_QV + qvbase + (size_t)d4 * TQ + tl) = w;
            }
        } else if (item < NK + NV + NR) {
            // ---------------- Residual item: one (k/v, bh) buffer ---------------
            const int ri   = item - NK - NV;
            const int half = ri >> 6;            // 0 = k, 1 = v
            const int bh   = ri & 63;

            const float* __restrict__ src =
                (half ? v : k) + (((size_t)bh) * S_ + TQ) * D_;
            float* __restrict__ dstf =
                out + (half ? OFF_VR : OFF_KR) + ((size_t)bh) * RROWS * D_;

            // rows 0..127: streaming copy, 4096 float4
            const float4* __restrict__ s4 = (const float4*)src;
            float4* __restrict__ d4p = (float4*)dstf;
#pragma unroll
            for (int j = 0; j < 8; j++)
                d4p[tid + j * 512] = s4[tid + j * 512];

            // rows 128..256: zero, 4128 float4
            float4* __restrict__ z4 = (float4*)(dstf + 128 * D_);
            const float4 z = make_float4(0.f, 0.f, 0.f, 0.f);
#pragma unroll
            for (int j = 0; j < 8; j++)
                z4[tid + j * 512] = z;
            if (tid < 32) z4[tid + 8 * 512] = z;
        } else {
            // ---------------- Full-cache chunk: zero (+ scatter if s_block 0) ---
            const int fi      = item - NK - NV - NR;       // 0..4095
            const int half    = fi >> 11;                  // 2048 chunks per half
            const int c       = fi & 2047;
            const int bh      = c >> 5;
            const int s_block = c & 31;

            float* __restrict__ dstf =
                out + (half ? OFF_VF : OFF_KF) +
                ((size_t)bh) * (S_ * D_) + (size_t)s_block * (128 * D_);
            float4* __restrict__ d4p = (float4*)dstf;

            const float4 z = make_float4(0.f, 0.f, 0.f, 0.f);
#pragma unroll
            for (int j = 0; j < 8; j++)
                d4p[tid + j * 512] = z;

            if (s_block == 0) {
                __syncthreads();   // order scatter after this CTA's zeroes
                const int b   = bh >> 5;
                const int off = cs[b] - qcs[b];            // 0..63, off+U <= 79
                const float* __restrict__ src =
                    (half ? vn : kn) + ((size_t)bh) * (U_ * D_);
                // 16 rows x 32 float4 = 512 float4: one per thread
                const int u  = tid >> 5;
                const int dd = tid & 31;
                *(float4*)(dstf + (size_t)(off + u) * D_ + dd * 4) =
                    *(const float4*)(src + (size_t)u * D_ + dd * 4);
            }
        }
    }
}

// ---------------------------------------------------------------------------
extern "C" void kernel_launch(void* const* d_in, const int* in_sizes, int n_in,
                              void* d_out, int out_size) {
    const float* k     = (const float*)d_in[0];
    const float* v     = (const float*)d_in[1];
    const float* k_new = (const float*)d_in[2];
    const float* v_new = (const float*)d_in[3];
    const int*   cs    = (const int*)d_in[4];
    const int*   qcs   = (const int*)d_in[5];
    float* out = (float*)d_out;

    (void)in_sizes; (void)n_in; (void)out_size;

    mega_kernel<<<GRID_, 512>>>(k, v, k_new, v_new, cs, qcs, out);
}

// round 10
// speedup vs baseline: 1.5028x; 1.1298x over previous
#include <cuda_runtime.h>
#include <cstdint>

// Problem constants (fixed shapes per reference setup_inputs)
#define B_    2
#define H_    32
#define S_    4096
#define D_    128
#define U_    16
#define TQ    3968        // S - RESID - (S % GROUP)
#define NG    31          // TQ / GROUP
#define RROWS 257         // 2*RESID + 1

// Output region offsets (float32 elements, concatenated in reference return order)
static constexpr size_t LEN_QK  = (size_t)B_ * H_ * (TQ / 4) * D_;   // 8,126,464
static constexpr size_t LEN_SC  = (size_t)B_ * H_ * NG * D_;         // 253,952
static constexpr size_t LEN_QV  = (size_t)B_ * H_ * (D_ / 4) * TQ;   // 8,126,464
static constexpr size_t LEN_VSC = (size_t)B_ * H_ * TQ;              // 253,952
static constexpr size_t LEN_R   = (size_t)B_ * H_ * RROWS * D_;      // 2,105,344
static constexpr size_t LEN_F   = (size_t)B_ * H_ * S_ * D_;         // 33,554,432 = 2^25

static constexpr size_t OFF_QK = 0;
static constexpr size_t OFF_KS = OFF_QK + LEN_QK;
static constexpr size_t OFF_KM = OFF_KS + LEN_SC;
static constexpr size_t OFF_QV = OFF_KM + LEN_SC;
static constexpr size_t OFF_VS = OFF_QV + LEN_QV;
static constexpr size_t OFF_VM = OFF_VS + LEN_VSC;
static constexpr size_t OFF_KR = OFF_VM + LEN_VSC;
static constexpr size_t OFF_VR = OFF_KR + LEN_R;
static constexpr size_t OFF_KF = OFF_VR + LEN_R;
static constexpr size_t OFF_VF = OFF_KF + LEN_F;

// Unified work list (sequential phases — fine-grained R/W mixing regressed in R4)
static constexpr int    NK        = B_ * H_ * NG;                 // 1984 k-quant groups
static constexpr int    NV        = B_ * H_ * NG;                 // 1984 v-quant groups
static constexpr size_t FILL_F4   = (2 * LEN_R + 2 * LEN_F) / 4;  // 17,829,888 float4s
static constexpr int    FILL_CHUNK = 4096;                        // float4s per item = 16384 floats
static constexpr int    RES_CHUNKS = (int)(2 * LEN_R / (4 * FILL_CHUNK)); // 257 exact
static constexpr int    NFILL     = (int)(FILL_F4 / FILL_CHUNK);  // 4353 (exact)
static constexpr int    NITEMS    = NK + NV + NFILL;              // 8321

static constexpr int GRID_ = 296;   // 2 CTAs/SM on 148 SMs

__global__ __launch_bounds__(512, 2)
void mega_kernel(const float* __restrict__ k, const float* __restrict__ v,
                 const float* __restrict__ kn, const float* __restrict__ vn,
                 const int* __restrict__ cs, const int* __restrict__ qcs,
                 float* __restrict__ out)
{
    __shared__ float2 smn[8][64];
    __shared__ float2 smx[8][64];
    __shared__ unsigned short smq[128][34];   // pitch 34: conflict-free transpose
    __shared__ float ssc[128];
    __shared__ float smin[128];

    const int tid = threadIdx.x;

    for (int item = blockIdx.x; item < NITEMS; item += GRID_) {
        if (item < NK) {
            // ---------------- K quant: group of 128 seq rows, per (b,h,g,d) ----
            __syncthreads();   // protect smn/smx reuse across items
            const int bh = item / NG;
            const int g  = item - bh * NG;
            const int d2 = tid & 63;          // float2 column, d = 2*d2
            const int q  = tid >> 6;          // 0..7, each owns 16 seq rows

            const float2* __restrict__ base = (const float2*)(
                k + (((size_t)bh) * S_ + (size_t)g * 128) * D_) + d2;

            float2 vals[16];
            float mnx = 3.4e38f, mny = 3.4e38f, mxx = -3.4e38f, mxy = -3.4e38f;
#pragma unroll
            for (int it = 0; it < 16; it++) {
                float2 x = base[(size_t)(q * 16 + it) * (D_ / 2)];
                vals[it] = x;
                mnx = fminf(mnx, x.x); mny = fminf(mny, x.y);
                mxx = fmaxf(mxx, x.x); mxy = fmaxf(mxy, x.y);
            }
            smn[q][d2] = make_float2(mnx, mny);
            smx[q][d2] = make_float2(mxx, mxy);
            __syncthreads();
#pragma unroll
            for (int p = 0; p < 8; p++) {
                float2 a = smn[p][d2], bb = smx[p][d2];
                mnx = fminf(mnx, a.x); mny = fminf(mny, a.y);
                mxx = fmaxf(mxx, bb.x); mxy = fmaxf(mxy, bb.y);
            }
            const float scx = fmaxf(__fdiv_rn(mxx - mnx, 15.0f), 1e-6f);
            const float scy = fmaxf(__fdiv_rn(mxy - mny, 15.0f), 1e-6f);
            const float ivx = __fdiv_rn(1.0f, scx);
            const float ivy = __fdiv_rn(1.0f, scy);

            if (q == 0) {
                size_t si = (((size_t)bh) * NG + g) * D_ + 2 * d2;
                *(float2*)(out + OFF_KS + si) = make_float2(scx, scy);
                *(float2*)(out + OFF_KM + si) = make_float2(mnx, mny);
            }

            float* __restrict__ po = out + OFF_QK;
            const size_t rowbase = ((size_t)bh) * (TQ / 4) + (size_t)g * 32 + (size_t)q * 4;
#pragma unroll
            for (int j = 0; j < 4; j++) {
                unsigned px = 0, py = 0;
#pragma unroll
                for (int n = 0; n < 4; n++) {
                    int cx = (int)rintf((vals[j * 4 + n].x - mnx) * ivx);
                    int cy = (int)rintf((vals[j * 4 + n].y - mny) * ivy);
                    cx = cx < 0 ? 0 : (cx > 15 ? 15 : cx);
                    cy = cy < 0 ? 0 : (cy > 15 ? 15 : cy);
                    px |= (unsigned)cx << (4 * n);
                    py |= (unsigned)cy << (4 * n);
                }
                *(float2*)(po + (rowbase + j) * D_ + 2 * d2) =
                    make_float2((float)px, (float)py);
            }
        } else if (item < NK + NV) {
            // ---------------- V quant: group = full head_dim, per token --------
            // All 8 tokens loaded up-front (MLP=8), then paired reductions.
            __syncthreads();   // protect smq/ssc/smin reuse across items
            const int vi = item - NK;
            const int bh = vi / NG;
            const int g  = vi - bh * NG;
            const int lane = tid & 31;
            const int warp = tid >> 5;       // 16 warps, 8 tokens each

            const float* __restrict__ base =
                v + (((size_t)bh) * S_ + (size_t)g * 128) * D_ + lane * 4;

            float4 va[8];
#pragma unroll
            for (int it = 0; it < 8; it++)
                va[it] = *(const float4*)(base + (size_t)(warp * 8 + it) * D_);

#pragma unroll
            for (int p = 0; p < 4; p++) {
                const int tl0 = warp * 8 + 2 * p;
                const int tl1 = tl0 + 1;
                float4 x0 = va[2 * p];
                float4 x1 = va[2 * p + 1];

                float mn0 = fminf(fminf(x0.x, x0.y), fminf(x0.z, x0.w));
                float mx0 = fmaxf(fmaxf(x0.x, x0.y), fmaxf(x0.z, x0.w));
                float mn1 = fminf(fminf(x1.x, x1.y), fminf(x1.z, x1.w));
                float mx1 = fmaxf(fmaxf(x1.x, x1.y), fmaxf(x1.z, x1.w));
#pragma unroll
                for (int o = 16; o > 0; o >>= 1) {
                    mn0 = fminf(mn0, __shfl_xor_sync(0xFFFFFFFFu, mn0, o));
                    mn1 = fminf(mn1, __shfl_xor_sync(0xFFFFFFFFu, mn1, o));
                    mx0 = fmaxf(mx0, __shfl_xor_sync(0xFFFFFFFFu, mx0, o));
                    mx1 = fmaxf(mx1, __shfl_xor_sync(0xFFFFFFFFu, mx1, o));
                }
                const float sc0 = fmaxf(__fdiv_rn(mx0 - mn0, 15.0f), 1e-6f);
                const float sc1 = fmaxf(__fdiv_rn(mx1 - mn1, 15.0f), 1e-6f);
                const float iv0 = __fdiv_rn(1.0f, sc0);
                const float iv1 = __fdiv_rn(1.0f, sc1);

                int a0 = (int)rintf((x0.x - mn0) * iv0);
                int a1 = (int)rintf((x0.y - mn0) * iv0);
                int a2 = (int)rintf((x0.z - mn0) * iv0);
                int a3 = (int)rintf((x0.w - mn0) * iv0);
                int b0 = (int)rintf((x1.x - mn1) * iv1);
                int b1 = (int)rintf((x1.y - mn1) * iv1);
                int b2 = (int)rintf((x1.z - mn1) * iv1);
                int b3 = (int)rintf((x1.w - mn1) * iv1);
                a0 = a0 < 0 ? 0 : (a0 > 15 ? 15 : a0);
                a1 = a1 < 0 ? 0 : (a1 > 15 ? 15 : a1);
                a2 = a2 < 0 ? 0 : (a2 > 15 ? 15 : a2);
                a3 = a3 < 0 ? 0 : (a3 > 15 ? 15 : a3);
                b0 = b0 < 0 ? 0 : (b0 > 15 ? 15 : b0);
                b1 = b1 < 0 ? 0 : (b1 > 15 ? 15 : b1);
                b2 = b2 < 0 ? 0 : (b2 > 15 ? 15 : b2);
                b3 = b3 < 0 ? 0 : (b3 > 15 ? 15 : b3);

                smq[tl0][lane] = (unsigned short)((unsigned)a0 | ((unsigned)a1 << 4) |
                                                 ((unsigned)a2 << 8) | ((unsigned)a3 << 12));
                smq[tl1][lane] = (unsigned short)((unsigned)b0 | ((unsigned)b1 << 4) |
                                                 ((unsigned)b2 << 8) | ((unsigned)b3 << 12));
                if (lane == 0) {
                    ssc[tl0] = sc0; smin[tl0] = mn0;
                    ssc[tl1] = sc1; smin[tl1] = mn1;
                }
            }
            __syncthreads();

            const size_t tbase = ((size_t)bh) * TQ + (size_t)g * 128;
            if (tid < 128) {
                out[OFF_VS + tbase + tid] = ssc[tid];
                out[OFF_VM + tbase + tid] = smin[tid];
            }
            // Vectorized transpose writeback: one float4 = 4 consecutive tokens.
            const size_t qvbase = ((size_t)bh) * 32 * TQ + (size_t)g * 128;
#pragma unroll
            for (int i = tid; i < 1024; i += 512) {
                const int d4 = i >> 5;        // 0..31
                const int tl = (i & 31) * 4;  // token base
                float4 w;
                w.x = (float)smq[tl + 0][d4];
                w.y = (float)smq[tl + 1][d4];
                w.z = (float)smq[tl + 2][d4];
                w.w = (float)smq[tl + 3][d4];
                *(float4*)(out + OFF_QV + qvbase + (size_t)d4 * TQ + tl) = w;
            }
        } else {
            // ---------------- Fill: zeros + residual tails + new-token scatter --
            const int fitem = item - NK - NV;
            float4* __restrict__ dst = (float4*)(out + OFF_KR);

            // Chunk geometry: 4096 float4 = 16384 floats. Residual region =
            // exactly 257 chunks. Full-cache region chunks are (bh,half,s_block)
            // aligned: 128 seq rows per chunk, 32 chunks per (half,bh). Scatter
            // rows (s < off+U <= 80) live only in s_block 0.
            bool pure_zero = false;
            if (fitem >= RES_CHUNKS) {
                const int c2 = fitem - RES_CHUNKS;
                pure_zero = (c2 & 31) != 0;       // s_block != 0 -> all zeros
            }

            const size_t base4 = (size_t)fitem * FILL_CHUNK;
            if (pure_zero) {
                // Store-only streaming path: no per-element math.
                const float4 z = make_float4(0.f, 0.f, 0.f, 0.f);
                float4* __restrict__ p = dst + base4 + tid;
#pragma unroll
                for (int j = 0; j < FILL_CHUNK / 512; j++)
                    p[j * 512] = z;
            } else {
                const int off0 = cs[0] - qcs[0];
                const int off1 = cs[1] - qcs[1];
#pragma unroll
                for (int j = 0; j < FILL_CHUNK / 512; j++) {
                    const size_t f  = base4 + tid + (size_t)j * 512;
                    const size_t fi = f * 4;   // float offset within fill region
                    float4 val = make_float4(0.f, 0.f, 0.f, 0.f);
                    if (fi < 2 * LEN_R) {
                        // residual buffers (B,H,257,D): rows 0..127 = tail copy
                        const int  half = fi >= LEN_R;
                        const size_t r  = fi - (half ? LEN_R : 0);
                        const int  bh   = (int)(r / (RROWS * D_));
                        const int  rr   = (int)(r - (size_t)bh * (RROWS * D_));
                        const int  row  = rr >> 7;
                        const int  d    = rr & 127;
                        if (row < 128) {
                            const float* __restrict__ src = half ? v : k;
                            val = *(const float4*)(src + (((size_t)bh) * S_ + TQ + row) * D_ + d);
                        }
                    } else {
                        // full caches: zeros + k_new/v_new at per-batch offset
                        const size_t fi2 = fi - 2 * LEN_R;
                        const int  half  = (int)(fi2 >> 25);       // LEN_F = 2^25
                        const size_t r   = fi2 & (LEN_F - 1);
                        const int  bh    = (int)(r >> 19);         // S_*D_ = 2^19
                        const int  s     = (int)((r >> 7) & (S_ - 1));
                        const int  d     = (int)(r & 127);
                        const int  b     = bh >> 5;                // H_ = 32
                        const int  u     = s - (b ? off1 : off0);
                        if ((unsigned)u < (unsigned)U_) {
                            const float* __restrict__ src = half ? vn : kn;
                            val = *(const float4*)(src + (((size_t)bh) * U_ + u) * D_ + d);
                        }
                    }
                    dst[f] = val;
                }
            }
        }
    }
}

// ---------------------------------------------------------------------------
extern "C" void kernel_launch(void* const* d_in, const int* in_sizes, int n_in,
                              void* d_out, int out_size) {
    const float* k     = (const float*)d_in[0];
    const float* v     = (const float*)d_in[1];
    const float* k_new = (const float*)d_in[2];
    const float* v_new = (const float*)d_in[3];
    const int*   cs    = (const int*)d_in[4];
    const int*   qcs   = (const int*)d_in[5];
    float* out = (float*)d_out;

    (void)in_sizes; (void)n_in; (void)out_size;

    mega_kernel<<<GRID_, 512>>>(k, v, k_new, v_new, cs, qcs, out);
}